// round 12
// baseline (speedup 1.0000x reference)
#include <cuda_runtime.h>

#define NN 64
#define CC 128
#define HH 64
#define WW 64
#define HID 8
#define NPLANE 9                       // 8 W_i2 rows + 1 bias plane

typedef unsigned long long u64;

// Packed fp32x2 ops (Blackwell FFMA2 — PTX-only, ptxas never auto-fuses)
static __device__ __forceinline__ u64 f2fma(u64 a, u64 b, u64 c) {
    u64 d;
    asm("fma.rn.f32x2 %0, %1, %2, %3;" : "=l"(d) : "l"(a), "l"(b), "l"(c));
    return d;
}
static __device__ __forceinline__ u64 f2add(u64 a, u64 b) {
    u64 d;
    asm("add.rn.f32x2 %0, %1, %2;" : "=l"(d) : "l"(a), "l"(b));
    return d;
}
static __device__ __forceinline__ u64 f2pack(float lo, float hi) {
    u64 d;
    asm("mov.b64 %0, {%1, %2};" : "=l"(d) : "f"(lo), "f"(hi));
    return d;
}
static __device__ __forceinline__ float2 f2unpack(u64 s) {
    float lo, hi;
    asm("mov.b64 {%0, %1}, %2;" : "=f"(lo), "=f"(hi) : "l"(s));
    return make_float2(lo, hi);
}

// Scratch (device globals). All fully rewritten every call -> deterministic.
__device__ float  g_hpart[NN][16][16];     // per-chunk proj partials (o1|i1)
__device__ float  g_ppart[NN][16][4];      // per-chunk per-wgroup sums
__device__ float  g_sp[NN][9];
__device__ float  g_co[NN][CC];
__device__ float  g_wz[NN][NPLANE];        // relu(h_i[j]), j<8; [8]=1
__device__ float4 g_y[NPLANE][NN * 1024];  // 9 reduced planes (float4 quads)
__device__ float  g_z[NN][HH][WW];         // final weighted combination

// ---------------------------------------------------------------------------
// Kernel A': SINGLE pass over x (134 MB), packed f32x2 math + explicit
// 4-deep LDG prefetch ring (next channel's load issued before the current
// channel's FMA chain -> MLP ~4 instead of ~1).
// Block = (chunk 0..15, n), 64 threads; thread owns quad q = chunk*64+t.
// ---------------------------------------------------------------------------
__global__ void __launch_bounds__(64, 8)
kA_fused(const float* __restrict__ x,
         const float* __restrict__ W_i2, const float* __restrict__ b_i2,
         const float* __restrict__ W_o1, const float* __restrict__ W_i1) {
    int chunk = blockIdx.x;            // 0..15
    int n     = blockIdx.y;
    int t     = threadIdx.x;           // 0..63
    int warp  = t >> 5;
    int lane  = t & 31;

    __shared__ __align__(16) u64 swA2[CC][10];   // [c][j]: (w,w) pairs, j<9
    __shared__ __align__(16) u64 swB2[CC][8];    // [c][k]: proj weight pairs
    __shared__ float stot[64];
    __shared__ float shp[2][16];

    for (int idx = t; idx < CC * NPLANE; idx += 64) {
        int c = idx / NPLANE, j = idx - c * NPLANE;
        float w = (j < 8) ? W_i2[j * CC + c] : b_i2[c];
        swA2[c][j] = f2pack(w, w);
    }
    for (int idx = t; idx < CC * 8; idx += 64) {
        int c = idx >> 3, k = idx & 7;
        float w0 = (k < 4) ? W_o1[c * HID + 2 * k]     : W_i1[c * HID + 2 * (k - 4)];
        float w1 = (k < 4) ? W_o1[c * HID + 2 * k + 1] : W_i1[c * HID + 2 * (k - 4) + 1];
        swB2[c][k] = f2pack(w0, w1);
    }
    __syncthreads();

    int q = chunk * 64 + t;            // float4 index within plane (0..1023)
    const float4* xp = (const float4*)x + (size_t)n * CC * 1024 + q;

    u64 acc[2 * NPLANE];               // [2j]=lanes(x,y), [2j+1]=lanes(z,w)
#pragma unroll
    for (int j = 0; j < 2 * NPLANE; ++j) acc[j] = 0ull;
    u64 hp2[8];
#pragma unroll
    for (int j = 0; j < 8; ++j) hp2[j] = 0ull;
    float tot = 0.f;

    // prefetch ring: 4 channels in flight
    float4 vbuf[4];
#pragma unroll
    for (int k = 0; k < 4; ++k)
        vbuf[k] = xp[(size_t)k * 1024];

    for (int cb = 0; cb < CC; cb += 4) {
#pragma unroll
        for (int k = 0; k < 4; ++k) {
            int c = cb + k;
            float4 v = vbuf[k];
            // issue next load BEFORE the consume chain (wrapped index is
            // always valid; the wrapped loads' results are never consumed)
            vbuf[k] = xp[(size_t)((cb + 4 + k) & (CC - 1)) * 1024];

            u64 vlo = f2pack(v.x, v.y);
            u64 vhi = f2pack(v.z, v.w);

#pragma unroll
            for (int j = 0; j < NPLANE; ++j) {
                u64 w = swA2[c][j];
                acc[2 * j]     = f2fma(w, vlo, acc[2 * j]);
                acc[2 * j + 1] = f2fma(w, vhi, acc[2 * j + 1]);
            }

            float2 sp2 = f2unpack(f2add(vlo, vhi));
            float s = sp2.x + sp2.y;
            tot += s;
            u64 s2 = f2pack(s, s);

#pragma unroll
            for (int j = 0; j < 8; ++j)
                hp2[j] = f2fma(swB2[c][j], s2, hp2[j]);
        }
    }

    // write the 9 reduced-plane quads
#pragma unroll
    for (int j = 0; j < NPLANE; ++j) {
        float2 lo = f2unpack(acc[2 * j]);
        float2 hi = f2unpack(acc[2 * j + 1]);
        g_y[j][n * 1024 + q] = make_float4(lo.x, lo.y, hi.x, hi.y);
    }

    // one-time warp reduce of the 16 projections, then cross-warp combine
#pragma unroll
    for (int k = 0; k < 8; ++k) {
        float2 h = f2unpack(hp2[k]);
#pragma unroll
        for (int off = 16; off >= 1; off >>= 1) {
            h.x += __shfl_xor_sync(0xFFFFFFFFu, h.x, off);
            h.y += __shfl_xor_sync(0xFFFFFFFFu, h.y, off);
        }
        if (lane == 0) { shp[warp][2 * k] = h.x; shp[warp][2 * k + 1] = h.y; }
    }
    stot[t] = tot;
    __syncthreads();

    if (t < 16) g_hpart[n][chunk][t] = shp[0][t] + shp[1][t];

    // pool partials: thread t -> local row r=t/16, quad qd=t%16, wgroup qd/4.
    if (t < 4) {
        float s = 0.f;
#pragma unroll
        for (int r = 0; r < 4; ++r)
#pragma unroll
            for (int k = 0; k < 4; ++k)
                s += stot[r * 16 + t * 4 + k];
        g_ppart[n][chunk][t] = s;
    }
}

// ---------------------------------------------------------------------------
// Kernel B: fold partials, finish MLPs. One block per n, 128 threads.
// ---------------------------------------------------------------------------
__global__ void kB_mlp(const float* __restrict__ W_sp, const float* __restrict__ b_sp,
                       const float* __restrict__ b_o1, const float* __restrict__ b_i1,
                       const float* __restrict__ W_o2, const float* __restrict__ b_o2) {
    int n = blockIdx.x;
    int t = threadIdx.x;               // 0..127

    __shared__ float sho[HID];
    __shared__ float sxs[16];

    if (t < 16) {
        float s = 0.f;
#pragma unroll
        for (int k = 0; k < 16; ++k) s += g_hpart[n][k][t];
        s *= (1.f / (CC * 32.f));      // 1/4096 = 1/(H*W)
        if (t < 8) sho[t] = fmaxf(s + b_o1[t], 0.f);
        else       g_wz[n][t - 8] = fmaxf(s + b_i1[t - 8], 0.f);
    }
    if (t == 16) g_wz[n][8] = 1.f;     // bias-plane weight
    if (t >= 32 && t < 48) {           // pooled xs
        int p = t - 32;
        int hg = p >> 2, wg = p & 3;
        float s = 0.f;
#pragma unroll
        for (int k = 0; k < 4; ++k) s += g_ppart[n][hg * 4 + k][wg];
        sxs[p] = s * (1.f / (256.f * CC));
    }
    __syncthreads();

    float a = b_o2[t];
#pragma unroll
    for (int j = 0; j < HID; ++j)
        a += sho[j] * W_o2[j * CC + t];
    g_co[n][t] = a;

    if (t < 9) {
        float s = b_sp[t];
#pragma unroll
        for (int p = 0; p < 16; ++p) s += sxs[p] * W_sp[p * 9 + t];
        g_sp[n][t] = s;
    }
}

// ---------------------------------------------------------------------------
// Kernel Z: z = sum_j wz[j] * y_j. 256 blocks x 256 threads; L2-hot (9.4MB).
// ---------------------------------------------------------------------------
__global__ void kZ_combine(void) {
    int b = blockIdx.x;                // 0..255
    int t = threadIdx.x;               // 0..255
    int n = b >> 2;                    // 4 blocks per n
    int q = (b & 3) * 256 + t;         // quad 0..1023

    __shared__ float swz[NPLANE];
    if (t < NPLANE) swz[t] = g_wz[n][t];
    __syncthreads();

    float4 acc = make_float4(0.f, 0.f, 0.f, 0.f);
#pragma unroll
    for (int j = 0; j < NPLANE; ++j) {
        float4 v = g_y[j][n * 1024 + q];
        float s = swz[j];
        acc.x += s * v.x; acc.y += s * v.y;
        acc.z += s * v.z; acc.w += s * v.w;
    }
    ((float4*)g_z)[n * 1024 + q] = acc;
}

// ---------------------------------------------------------------------------
// Fused kernel DE: conv3x3 tile + 32-channel scaled store sweep.
// grid (8, NN, 4) = 2048 blocks, 256 threads. Streaming stores.
// ---------------------------------------------------------------------------
__global__ void kDE_convscale(float4* __restrict__ out) {
    int chunk = blockIdx.x;            // 0..7 -> output rows [chunk*8, +8)
    int n     = blockIdx.y;
    int ogrp  = blockIdx.z;            // 0..3 -> o in [ogrp*32, +32)
    int t     = threadIdx.x;           // 0..255

    __shared__ float sz[10][WW];
    __shared__ float st[8][WW];
    __shared__ float sco[32];
    __shared__ float ssp[9];

    int r0 = chunk * 8;

    if (t < 160) {
        int rr = t >> 4, qq = t & 15;
        int h = r0 - 1 + rr;
        float4 v = make_float4(0.f, 0.f, 0.f, 0.f);
        if (h >= 0 && h < HH)
            v = ((const float4*)g_z)[(n * HH + h) * 16 + qq];
        ((float4*)&sz[rr][0])[qq] = v;
    }
    if (t >= 192 && t < 224) sco[t - 192] = g_co[n][ogrp * 32 + (t - 192)];
    if (t >= 240 && t < 249) ssp[t - 240] = g_sp[n][t - 240];
    __syncthreads();

#pragma unroll
    for (int k = 0; k < 2; ++k) {
        int p = t + k * 256;           // 0..511
        int h = p >> 6, w = p & 63;
        float acc = 0.f;
#pragma unroll
        for (int kh = 0; kh < 3; ++kh) {
#pragma unroll
            for (int kw = 0; kw < 3; ++kw) {
                int ww = w + kw - 1;
                if (ww >= 0 && ww < WW)
                    acc += ssp[kh * 3 + kw] * sz[h + kh][ww];
            }
        }
        st[h][w] = acc;
    }
    __syncthreads();

    int q  = t & 127;
    int os = t >> 7;
    float4 v = ((const float4*)st)[q];
    int rr = q >> 4, qq = q & 15;

    int o0 = ogrp * 32 + os * 16;
    size_t base = ((size_t)n * CC + o0) * (HH * WW / 4)
                + (size_t)(r0 + rr) * 16 + qq;
#pragma unroll 4
    for (int o = 0; o < 16; ++o) {
        float s = sco[os * 16 + o];
        float4 ov;
        ov.x = v.x * s; ov.y = v.y * s; ov.z = v.z * s; ov.w = v.w * s;
        __stcs(&out[base + (size_t)o * (HH * WW / 4)], ov);
    }
}

// ---------------------------------------------------------------------------
extern "C" void kernel_launch(void* const* d_in, const int* in_sizes, int n_in,
                              void* d_out, int out_size) {
    const float* x    = (const float*)d_in[0];
    const float* W_sp = (const float*)d_in[1];
    const float* b_sp = (const float*)d_in[2];
    const float* W_o1 = (const float*)d_in[3];
    const float* b_o1 = (const float*)d_in[4];
    const float* W_o2 = (const float*)d_in[5];
    const float* b_o2 = (const float*)d_in[6];
    const float* W_i1 = (const float*)d_in[7];
    const float* b_i1 = (const float*)d_in[8];
    const float* W_i2 = (const float*)d_in[9];
    const float* b_i2 = (const float*)d_in[10];

    {
        dim3 g(16, NN);
        kA_fused<<<g, 64>>>(x, W_i2, b_i2, W_o1, W_i1);
    }
    kB_mlp<<<NN, CC>>>(W_sp, b_sp, b_o1, b_i1, W_o2, b_o2);
    kZ_combine<<<256, 256>>>();
    {
        dim3 g(8, NN, 4);
        kDE_convscale<<<g, 256>>>((float4*)d_out);
    }
}

// round 14
// speedup vs baseline: 1.1104x; 1.1104x over previous
#include <cuda_runtime.h>

#define NN 64
#define CC 128
#define HH 64
#define WW 64
#define HID 8
#define NPLANE 9                       // 8 W_i2 rows + 1 bias plane
#define STAGES 8

typedef unsigned long long u64;

// Packed fp32x2 ops (Blackwell FFMA2 — PTX-only, ptxas never auto-fuses)
static __device__ __forceinline__ u64 f2fma(u64 a, u64 b, u64 c) {
    u64 d;
    asm("fma.rn.f32x2 %0, %1, %2, %3;" : "=l"(d) : "l"(a), "l"(b), "l"(c));
    return d;
}
static __device__ __forceinline__ u64 f2add(u64 a, u64 b) {
    u64 d;
    asm("add.rn.f32x2 %0, %1, %2;" : "=l"(d) : "l"(a), "l"(b));
    return d;
}
static __device__ __forceinline__ u64 f2pack(float lo, float hi) {
    u64 d;
    asm("mov.b64 %0, {%1, %2};" : "=l"(d) : "f"(lo), "f"(hi));
    return d;
}
static __device__ __forceinline__ float2 f2unpack(u64 s) {
    float lo, hi;
    asm("mov.b64 {%0, %1}, %2;" : "=f"(lo), "=f"(hi) : "l"(s));
    return make_float2(lo, hi);
}
static __device__ __forceinline__ unsigned smem_u32(const void* p) {
    unsigned a;
    asm("{ .reg .u64 tmp; cvta.to.shared.u64 tmp, %1; cvt.u32.u64 %0, tmp; }"
        : "=r"(a) : "l"(p));
    return a;
}
// 16B async copy, L2-only caching (bypasses L1 fill on the way in)
#define CP16(saddr, gptr) \
    asm volatile("cp.async.cg.shared.global [%0], [%1], 16;" \
                 :: "r"(saddr), "l"(gptr) : "memory")
#define CP_COMMIT() asm volatile("cp.async.commit_group;" ::: "memory")
#define CP_WAIT7()  asm volatile("cp.async.wait_group 7;" ::: "memory")

// Scratch (device globals). All fully rewritten every call -> deterministic.
__device__ float  g_hpart[NN][16][16];     // per-chunk proj partials (o1|i1)
__device__ float  g_ppart[NN][16][4];      // per-chunk per-wgroup sums
__device__ float  g_sp[NN][9];
__device__ float  g_co[NN][CC];
__device__ float  g_wz[NN][NPLANE];        // relu(h_i[j]), j<8; [8]=1
__device__ float4 g_y[NPLANE][NN * 1024];  // 9 reduced planes (float4 quads)
__device__ float  g_z[NN][HH][WW];         // final weighted combination

// ---------------------------------------------------------------------------
// Kernel A': SINGLE pass over x (134 MB). Channel loads staged through an
// 8-deep cp.async ring: commit-group per channel, wait_group 7 -> 7 channels
// ALWAYS in flight regardless of ptxas scoreboard allocation (fix for the
// failed register-prefetch ring: LDGSTS completion is per commit-group,
// not per destination register).
// Block = (chunk 0..15, n), 64 threads; thread owns quad q = chunk*64+t and
// reads back only its own staged quad -> no intra-loop __syncthreads.
// ---------------------------------------------------------------------------
__global__ void __launch_bounds__(64, 8)
kA_fused(const float* __restrict__ x,
         const float* __restrict__ W_i2, const float* __restrict__ b_i2,
         const float* __restrict__ W_o1, const float* __restrict__ W_i1) {
    int chunk = blockIdx.x;            // 0..15
    int n     = blockIdx.y;
    int t     = threadIdx.x;           // 0..63
    int warp  = t >> 5;
    int lane  = t & 31;

    __shared__ __align__(16) float4 sbuf[STAGES][64];  // 8 KB stage ring
    __shared__ u64 swA2[CC][NPLANE];   // [c][j]: (w,w) pairs
    __shared__ u64 swB2[CC][8];        // [c][k]: proj weight pairs
    __shared__ float stot[64];
    __shared__ float shp[2][16];

    for (int idx = t; idx < CC * NPLANE; idx += 64) {
        int c = idx / NPLANE, j = idx - c * NPLANE;
        float w = (j < 8) ? W_i2[j * CC + c] : b_i2[c];
        swA2[c][j] = f2pack(w, w);
    }
    for (int idx = t; idx < CC * 8; idx += 64) {
        int c = idx >> 3, k = idx & 7;
        float w0 = (k < 4) ? W_o1[c * HID + 2 * k]     : W_i1[c * HID + 2 * (k - 4)];
        float w1 = (k < 4) ? W_o1[c * HID + 2 * k + 1] : W_i1[c * HID + 2 * (k - 4) + 1];
        swB2[c][k] = f2pack(w0, w1);
    }
    __syncthreads();

    int q = chunk * 64 + t;            // float4 index within plane (0..1023)
    const float4* xp = (const float4*)x + (size_t)n * CC * 1024 + q;
    unsigned sb = smem_u32(&sbuf[0][0]) + (unsigned)t * 16u;

    u64 acc[2 * NPLANE];
#pragma unroll
    for (int j = 0; j < 2 * NPLANE; ++j) acc[j] = 0ull;
    u64 hp2[8];
#pragma unroll
    for (int j = 0; j < 8; ++j) hp2[j] = 0ull;
    float tot = 0.f;

    // prologue: stage channels 0..6, one commit-group per channel
#pragma unroll
    for (int s = 0; s < STAGES - 1; ++s) {
        CP16(sb + (unsigned)(s << 10), xp + (size_t)s * 1024);
        CP_COMMIT();
    }

    for (int c = 0; c < CC; ++c) {
        int cn = c + STAGES - 1;       // channel to stage this iteration
        if (cn < CC)
            CP16(sb + (unsigned)((cn & (STAGES - 1)) << 10),
                 xp + (size_t)cn * 1024);
        CP_COMMIT();                   // group index stays == channel index
        CP_WAIT7();                    // stage c complete (7 groups in flight)

        float4 v = sbuf[c & (STAGES - 1)][t];
        u64 vlo = f2pack(v.x, v.y);
        u64 vhi = f2pack(v.z, v.w);

#pragma unroll
        for (int j = 0; j < NPLANE; ++j) {
            u64 w = swA2[c][j];
            acc[2 * j]     = f2fma(w, vlo, acc[2 * j]);
            acc[2 * j + 1] = f2fma(w, vhi, acc[2 * j + 1]);
        }

        float2 sp2 = f2unpack(f2add(vlo, vhi));
        float s = sp2.x + sp2.y;
        tot += s;
        u64 s2 = f2pack(s, s);

#pragma unroll
        for (int j = 0; j < 8; ++j)
            hp2[j] = f2fma(swB2[c][j], s2, hp2[j]);
    }

    // write the 9 reduced-plane quads
#pragma unroll
    for (int j = 0; j < NPLANE; ++j) {
        float2 lo = f2unpack(acc[2 * j]);
        float2 hi = f2unpack(acc[2 * j + 1]);
        g_y[j][n * 1024 + q] = make_float4(lo.x, lo.y, hi.x, hi.y);
    }

    // one-time warp reduce of the 16 projections, then cross-warp combine
#pragma unroll
    for (int k = 0; k < 8; ++k) {
        float2 h = f2unpack(hp2[k]);
#pragma unroll
        for (int off = 16; off >= 1; off >>= 1) {
            h.x += __shfl_xor_sync(0xFFFFFFFFu, h.x, off);
            h.y += __shfl_xor_sync(0xFFFFFFFFu, h.y, off);
        }
        if (lane == 0) { shp[warp][2 * k] = h.x; shp[warp][2 * k + 1] = h.y; }
    }
    stot[t] = tot;
    __syncthreads();

    if (t < 16) g_hpart[n][chunk][t] = shp[0][t] + shp[1][t];

    // pool partials: thread t -> local row r=t/16, quad qd=t%16, wgroup qd/4.
    if (t < 4) {
        float s = 0.f;
#pragma unroll
        for (int r = 0; r < 4; ++r)
#pragma unroll
            for (int k = 0; k < 4; ++k)
                s += stot[r * 16 + t * 4 + k];
        g_ppart[n][chunk][t] = s;
    }
}

// ---------------------------------------------------------------------------
// Kernel B: fold partials, finish MLPs. One block per n, 128 threads.
// ---------------------------------------------------------------------------
__global__ void kB_mlp(const float* __restrict__ W_sp, const float* __restrict__ b_sp,
                       const float* __restrict__ b_o1, const float* __restrict__ b_i1,
                       const float* __restrict__ W_o2, const float* __restrict__ b_o2) {
    int n = blockIdx.x;
    int t = threadIdx.x;               // 0..127

    __shared__ float sho[HID];
    __shared__ float sxs[16];

    if (t < 16) {
        float s = 0.f;
#pragma unroll
        for (int k = 0; k < 16; ++k) s += g_hpart[n][k][t];
        s *= (1.f / (CC * 32.f));      // 1/4096 = 1/(H*W)
        if (t < 8) sho[t] = fmaxf(s + b_o1[t], 0.f);
        else       g_wz[n][t - 8] = fmaxf(s + b_i1[t - 8], 0.f);
    }
    if (t == 16) g_wz[n][8] = 1.f;     // bias-plane weight
    if (t >= 32 && t < 48) {           // pooled xs
        int p = t - 32;
        int hg = p >> 2, wg = p & 3;
        float s = 0.f;
#pragma unroll
        for (int k = 0; k < 4; ++k) s += g_ppart[n][hg * 4 + k][wg];
        sxs[p] = s * (1.f / (256.f * CC));
    }
    __syncthreads();

    float a = b_o2[t];
#pragma unroll
    for (int j = 0; j < HID; ++j)
        a += sho[j] * W_o2[j * CC + t];
    g_co[n][t] = a;

    if (t < 9) {
        float s = b_sp[t];
#pragma unroll
        for (int p = 0; p < 16; ++p) s += sxs[p] * W_sp[p * 9 + t];
        g_sp[n][t] = s;
    }
}

// ---------------------------------------------------------------------------
// Kernel Z: z = sum_j wz[j] * y_j. 256 blocks x 256 threads; L2-hot (9.4MB).
// ---------------------------------------------------------------------------
__global__ void kZ_combine(void) {
    int b = blockIdx.x;                // 0..255
    int t = threadIdx.x;               // 0..255
    int n = b >> 2;                    // 4 blocks per n
    int q = (b & 3) * 256 + t;         // quad 0..1023

    __shared__ float swz[NPLANE];
    if (t < NPLANE) swz[t] = g_wz[n][t];
    __syncthreads();

    float4 acc = make_float4(0.f, 0.f, 0.f, 0.f);
#pragma unroll
    for (int j = 0; j < NPLANE; ++j) {
        float4 v = g_y[j][n * 1024 + q];
        float s = swz[j];
        acc.x += s * v.x; acc.y += s * v.y;
        acc.z += s * v.z; acc.w += s * v.w;
    }
    ((float4*)g_z)[n * 1024 + q] = acc;
}

// ---------------------------------------------------------------------------
// Fused kernel DE: conv3x3 tile + 32-channel scaled store sweep.
// grid (8, NN, 4) = 2048 blocks, 256 threads. Streaming stores.
// ---------------------------------------------------------------------------
__global__ void kDE_convscale(float4* __restrict__ out) {
    int chunk = blockIdx.x;            // 0..7 -> output rows [chunk*8, +8)
    int n     = blockIdx.y;
    int ogrp  = blockIdx.z;            // 0..3 -> o in [ogrp*32, +32)
    int t     = threadIdx.x;           // 0..255

    __shared__ float sz[10][WW];
    __shared__ float st[8][WW];
    __shared__ float sco[32];
    __shared__ float ssp[9];

    int r0 = chunk * 8;

    if (t < 160) {
        int rr = t >> 4, qq = t & 15;
        int h = r0 - 1 + rr;
        float4 v = make_float4(0.f, 0.f, 0.f, 0.f);
        if (h >= 0 && h < HH)
            v = ((const float4*)g_z)[(n * HH + h) * 16 + qq];
        ((float4*)&sz[rr][0])[qq] = v;
    }
    if (t >= 192 && t < 224) sco[t - 192] = g_co[n][ogrp * 32 + (t - 192)];
    if (t >= 240 && t < 249) ssp[t - 240] = g_sp[n][t - 240];
    __syncthreads();

#pragma unroll
    for (int k = 0; k < 2; ++k) {
        int p = t + k * 256;           // 0..511
        int h = p >> 6, w = p & 63;
        float acc = 0.f;
#pragma unroll
        for (int kh = 0; kh < 3; ++kh) {
#pragma unroll
            for (int kw = 0; kw < 3; ++kw) {
                int ww = w + kw - 1;
                if (ww >= 0 && ww < WW)
                    acc += ssp[kh * 3 + kw] * sz[h + kh][ww];
            }
        }
        st[h][w] = acc;
    }
    __syncthreads();

    int q  = t & 127;
    int os = t >> 7;
    float4 v = ((const float4*)st)[q];
    int rr = q >> 4, qq = q & 15;

    int o0 = ogrp * 32 + os * 16;
    size_t base = ((size_t)n * CC + o0) * (HH * WW / 4)
                + (size_t)(r0 + rr) * 16 + qq;
#pragma unroll 4
    for (int o = 0; o < 16; ++o) {
        float s = sco[os * 16 + o];
        float4 ov;
        ov.x = v.x * s; ov.y = v.y * s; ov.z = v.z * s; ov.w = v.w * s;
        __stcs(&out[base + (size_t)o * (HH * WW / 4)], ov);
    }
}

// ---------------------------------------------------------------------------
extern "C" void kernel_launch(void* const* d_in, const int* in_sizes, int n_in,
                              void* d_out, int out_size) {
    const float* x    = (const float*)d_in[0];
    const float* W_sp = (const float*)d_in[1];
    const float* b_sp = (const float*)d_in[2];
    const float* W_o1 = (const float*)d_in[3];
    const float* b_o1 = (const float*)d_in[4];
    const float* W_o2 = (const float*)d_in[5];
    const float* b_o2 = (const float*)d_in[6];
    const float* W_i1 = (const float*)d_in[7];
    const float* b_i1 = (const float*)d_in[8];
    const float* W_i2 = (const float*)d_in[9];
    const float* b_i2 = (const float*)d_in[10];

    {
        dim3 g(16, NN);
        kA_fused<<<g, 64>>>(x, W_i2, b_i2, W_o1, W_i1);
    }
    kB_mlp<<<NN, CC>>>(W_sp, b_sp, b_o1, b_i1, W_o2, b_o2);
    kZ_combine<<<256, 256>>>();
    {
        dim3 g(8, NN, 4);
        kDE_convscale<<<g, 256>>>((float4*)d_out);
    }
}